// round 7
// baseline (speedup 1.0000x reference)
#include <cuda_runtime.h>

#define H 4096
#define E 8
#define H4 1024                    // float4 per row
#define TPB 256
#define ROWS_PER_BLOCK 4           // 8 warps, 2 warps per row
#define GRID (H / ROWS_PER_BLOCK)  // 1024 blocks
#define HALFF 2048                 // floats per half-row

__device__ unsigned long long g_best;  // (sortable_logit << 32) | (7 - e); 0 == -inf sentinel
__device__ int g_rcnt;                 // router blocks completed (0..8)
__device__ int g_done;                 // blocks finished (self-reset)

__device__ __forceinline__ unsigned int f2sortable(float f) {
    unsigned int u = __float_as_uint(f);
    return (u & 0x80000000u) ? ~u : (u | 0x80000000u);
}

// 256-bit load, keep resident in L2 across graph replays (gate_w)
__device__ __forceinline__ void ldg8_last(const float* p, float4& a, float4& b) {
    unsigned u0,u1,u2,u3,u4,u5,u6,u7;
    asm("ld.global.L2::evict_last.v8.b32 {%0,%1,%2,%3,%4,%5,%6,%7}, [%8];"
        : "=r"(u0),"=r"(u1),"=r"(u2),"=r"(u3),
          "=r"(u4),"=r"(u5),"=r"(u6),"=r"(u7)
        : "l"(p));
    a.x=__uint_as_float(u0); a.y=__uint_as_float(u1);
    a.z=__uint_as_float(u2); a.w=__uint_as_float(u3);
    b.x=__uint_as_float(u4); b.y=__uint_as_float(u5);
    b.z=__uint_as_float(u6); b.w=__uint_as_float(u7);
}
// 256-bit load, streaming / evict first (expert_w)
__device__ __forceinline__ void ldg8_first(const float* p, float4& a, float4& b) {
    unsigned u0,u1,u2,u3,u4,u5,u6,u7;
    asm("ld.global.L2::evict_first.v8.b32 {%0,%1,%2,%3,%4,%5,%6,%7}, [%8];"
        : "=r"(u0),"=r"(u1),"=r"(u2),"=r"(u3),
          "=r"(u4),"=r"(u5),"=r"(u6),"=r"(u7)
        : "l"(p));
    a.x=__uint_as_float(u0); a.y=__uint_as_float(u1);
    a.z=__uint_as_float(u2); a.w=__uint_as_float(u3);
    b.x=__uint_as_float(u4); b.y=__uint_as_float(u5);
    b.z=__uint_as_float(u6); b.w=__uint_as_float(u7);
}

__global__ void __launch_bounds__(TPB) fused_kernel(
    const float* __restrict__ x,
    const float* __restrict__ expert_w,
    const float* __restrict__ expert_b,
    const float* __restrict__ router_w,
    const float* __restrict__ router_b,
    const float* __restrict__ gate_w,
    const float* __restrict__ gate_b,
    float* __restrict__ out) {

    const int wid  = threadIdx.x >> 5;
    const int lane = threadIdx.x & 31;
    const float4* x4 = (const float4*)x;

    __shared__ float s_red[8];

    // ---- Blocks 0..7: router — one expert per block (16 KB dot) ----
    if (blockIdx.x < E) {
        const int e = blockIdx.x;
        const float4* w4 = (const float4*)(router_w + (size_t)e * H);
        float s = 0.f;
        #pragma unroll
        for (int k = 0; k < H4 / TPB; k++) {
            int i = threadIdx.x + k * TPB;
            float4 a = x4[i];
            float4 b = w4[i];
            s += a.x * b.x + a.y * b.y + a.z * b.z + a.w * b.w;
        }
        #pragma unroll
        for (int o = 16; o > 0; o >>= 1) s += __shfl_xor_sync(0xFFFFFFFFu, s, o);
        if (lane == 0) s_red[wid] = s;
        __syncthreads();
        if (threadIdx.x == 0) {
            float v = router_b[e];
            #pragma unroll
            for (int w = 0; w < 8; w++) v += s_red[w];
            unsigned long long key =
                ((unsigned long long)f2sortable(v) << 32) | (unsigned long long)(7 - e);
            atomicMax(&g_best, key);
            __threadfence();
            atomicAdd(&g_rcnt, 1);
        }
        __syncthreads();
    }

    // ---- All blocks: 4 rows, 2 warps per row (split-K halves) ----
    const int row   = blockIdx.x * ROWS_PER_BLOCK + (wid >> 1);
    const int half  = wid & 1;
    const int baseF = half * HALFF;     // float offset of this half
    const int base4 = half * (HALFF/4); // float4 offset of this half

    // Phase 1: gate dot (evict_last). 8 k-steps of 256 floats/warp; batch 4.
    const float* gw = gate_w + (size_t)row * H + baseF;
    float sg = 0.f;
    #pragma unroll
    for (int grp = 0; grp < 2; grp++) {
        float4 wa[4], wb[4];
        #pragma unroll
        for (int j = 0; j < 4; j++) {
            int k = grp * 4 + j;
            ldg8_last(gw + k * 256 + lane * 8, wa[j], wb[j]);
        }
        #pragma unroll
        for (int j = 0; j < 4; j++) {
            int k = grp * 4 + j;
            const float4* xp = x4 + base4 + k * 64 + lane * 2;
            float4 xa = xp[0], xb = xp[1];
            sg += xa.x*wa[j].x + xa.y*wa[j].y + xa.z*wa[j].z + xa.w*wa[j].w
                + xb.x*wb[j].x + xb.y*wb[j].y + xb.z*wb[j].z + xb.w*wb[j].w;
        }
    }

    // Wait for router result (gate phase >> router latency)
    int idx;
    if (lane == 0) {
        while (*(volatile int*)&g_rcnt < E) { __nanosleep(20); }
        __threadfence();
        unsigned long long b = *(volatile unsigned long long*)&g_best;
        idx = 7 - (int)(b & 7ULL);
    }
    idx = __shfl_sync(0xFFFFFFFFu, idx, 0);

    // Phase 2: expert dot (evict_first)
    const float* ew = expert_w + ((size_t)idx * H + row) * H + baseF;
    float se = 0.f;
    #pragma unroll
    for (int grp = 0; grp < 2; grp++) {
        float4 wa[4], wb[4];
        #pragma unroll
        for (int j = 0; j < 4; j++) {
            int k = grp * 4 + j;
            ldg8_first(ew + k * 256 + lane * 8, wa[j], wb[j]);
        }
        #pragma unroll
        for (int j = 0; j < 4; j++) {
            int k = grp * 4 + j;
            const float4* xp = x4 + base4 + k * 64 + lane * 2;
            float4 xa = xp[0], xb = xp[1];
            se += xa.x*wa[j].x + xa.y*wa[j].y + xa.z*wa[j].z + xa.w*wa[j].w
                + xb.x*wb[j].x + xb.y*wb[j].y + xb.z*wb[j].z + xb.w*wb[j].w;
        }
    }

    // Warp reductions
    #pragma unroll
    for (int o = 16; o > 0; o >>= 1) {
        sg += __shfl_xor_sync(0xFFFFFFFFu, sg, o);
        se += __shfl_xor_sync(0xFFFFFFFFu, se, o);
    }

    // Combine the two half-row partials via smem
    __shared__ float s_se[8], s_sg[8];
    if (lane == 0) { s_se[wid] = se; s_sg[wid] = sg; }
    __syncthreads();

    if ((wid & 1) == 0 && lane == 0) {
        float SE = s_se[wid] + s_se[wid + 1];
        float SG = s_sg[wid] + s_sg[wid + 1];
        float mix = tanhf(SE + expert_b[(size_t)idx * H + row]);
        float z = SG + gate_b[row];
        float g = 1.f / (1.f + expf(-z));
        float xv = x[row];
        out[row] = g * mix + (1.f - g) * xv;
    }

    // Self-cleaning reset: last block restores globals for the next replay
    __syncthreads();
    if (threadIdx.x == 0) {
        int d = atomicAdd(&g_done, 1);
        if (d == GRID - 1) {
            g_done = 0;
            g_rcnt = 0;
            g_best = 0ULL;
            __threadfence();
        }
    }
}

extern "C" void kernel_launch(void* const* d_in, const int* in_sizes, int n_in,
                              void* d_out, int out_size) {
    const float* x        = (const float*)d_in[0];  // [1, H]
    const float* expert_w = (const float*)d_in[1];  // [E, H, H]
    const float* expert_b = (const float*)d_in[2];  // [E, H]
    const float* router_w = (const float*)d_in[3];  // [E, H]
    const float* router_b = (const float*)d_in[4];  // [E]
    const float* gate_w   = (const float*)d_in[5];  // [H, H]
    const float* gate_b   = (const float*)d_in[6];  // [H]
    float* out = (float*)d_out;                     // [1, H]

    fused_kernel<<<GRID, TPB>>>(x, expert_w, expert_b, router_w, router_b,
                                gate_w, gate_b, out);
}

// round 11
// speedup vs baseline: 1.2731x; 1.2731x over previous
#include <cuda_runtime.h>

#define H 4096
#define E 8
#define H4 1024                 // float4 per row
#define TPB 256
#define GRID H                  // one block per output row
#define ITERS (H4 / TPB)        // 4

__device__ unsigned long long g_best;  // (sortable_logit << 32) | (7 - e); 0 == -inf sentinel
__device__ int g_rcnt;                 // router blocks completed (0..8)
__device__ int g_done;                 // blocks finished (self-reset)

__device__ __forceinline__ unsigned int f2sortable(float f) {
    unsigned int u = __float_as_uint(f);
    return (u & 0x80000000u) ? ~u : (u | 0x80000000u);
}

// 128-bit load with L2 cache-hint policy (legal v4 form, unlike bare L2::evict_*)
__device__ __forceinline__ float4 ldg4_pol(const float4* p, unsigned long long pol) {
    float4 v;
    asm("ld.global.L2::cache_hint.v4.f32 {%0,%1,%2,%3}, [%4], %5;"
        : "=f"(v.x), "=f"(v.y), "=f"(v.z), "=f"(v.w)
        : "l"(p), "l"(pol));
    return v;
}

__global__ void __launch_bounds__(TPB) fused_kernel(
    const float* __restrict__ x,
    const float* __restrict__ expert_w,
    const float* __restrict__ expert_b,
    const float* __restrict__ router_w,
    const float* __restrict__ router_b,
    const float* __restrict__ gate_w,
    const float* __restrict__ gate_b,
    float* __restrict__ out) {

    const int wid  = threadIdx.x >> 5;
    const int lane = threadIdx.x & 31;
    const int row  = blockIdx.x;
    const float4* x4 = (const float4*)x;

    // L2 policies: gate_w persists across replays, expert_w streams through
    unsigned long long pol_last, pol_first;
    asm("createpolicy.fractional.L2::evict_last.b64 %0, 1.0;"  : "=l"(pol_last));
    asm("createpolicy.fractional.L2::evict_first.b64 %0, 1.0;" : "=l"(pol_first));

    __shared__ float s_red[8];

    // ---- Blocks 0..7: router — one expert per block (16 KB dot) ----
    if (blockIdx.x < E) {
        const int e = blockIdx.x;
        const float4* w4 = (const float4*)(router_w + (size_t)e * H);
        float s = 0.f;
        #pragma unroll
        for (int k = 0; k < ITERS; k++) {
            int i = threadIdx.x + k * TPB;
            float4 a = x4[i];
            float4 b = w4[i];
            s += a.x * b.x + a.y * b.y + a.z * b.z + a.w * b.w;
        }
        #pragma unroll
        for (int o = 16; o > 0; o >>= 1) s += __shfl_xor_sync(0xFFFFFFFFu, s, o);
        if (lane == 0) s_red[wid] = s;
        __syncthreads();
        if (threadIdx.x == 0) {
            float v = router_b[e];
            #pragma unroll
            for (int w = 0; w < 8; w++) v += s_red[w];
            unsigned long long key =
                ((unsigned long long)f2sortable(v) << 32) | (unsigned long long)(7 - e);
            atomicMax(&g_best, key);
            __threadfence();
            atomicAdd(&g_rcnt, 1);
        }
        __syncthreads();   // s_red safe for reuse
    }

    // ---- Phase 1: gate dot (evict_last), loads front-batched ----
    const float4* g4 = (const float4*)(gate_w + (size_t)row * H);
    float4 xa[ITERS], ga[ITERS];
    #pragma unroll
    for (int k = 0; k < ITERS; k++) {
        int i = threadIdx.x + k * TPB;
        xa[k] = x4[i];
        ga[k] = ldg4_pol(g4 + i, pol_last);
    }
    float sg = 0.f;
    #pragma unroll
    for (int k = 0; k < ITERS; k++) {
        sg += xa[k].x * ga[k].x + xa[k].y * ga[k].y
            + xa[k].z * ga[k].z + xa[k].w * ga[k].w;
    }

    // ---- Wait for router result (router blocks scheduled first; gate phase
    //      covers router latency, so this is ~free) ----
    int idx;
    if (lane == 0) {
        while (*(volatile int*)&g_rcnt < E) { __nanosleep(20); }
        __threadfence();
        unsigned long long b = *(volatile unsigned long long*)&g_best;
        idx = 7 - (int)(b & 7ULL);
    }
    idx = __shfl_sync(0xFFFFFFFFu, idx, 0);

    // ---- Phase 2: expert dot (evict_first) ----
    const float4* e4 = (const float4*)(expert_w + ((size_t)idx * H + row) * H);
    float4 ea[ITERS];
    #pragma unroll
    for (int k = 0; k < ITERS; k++) {
        int i = threadIdx.x + k * TPB;
        ea[k] = ldg4_pol(e4 + i, pol_first);
    }
    float se = 0.f;
    #pragma unroll
    for (int k = 0; k < ITERS; k++) {
        se += xa[k].x * ea[k].x + xa[k].y * ea[k].y
            + xa[k].z * ea[k].z + xa[k].w * ea[k].w;
    }

    // ---- Reductions (R2 pattern) ----
    #pragma unroll
    for (int o = 16; o > 0; o >>= 1) {
        sg += __shfl_xor_sync(0xFFFFFFFFu, sg, o);
        se += __shfl_xor_sync(0xFFFFFFFFu, se, o);
    }

    __shared__ float re[TPB / 32], rg[TPB / 32];
    if (lane == 0) { re[wid] = se; rg[wid] = sg; }
    __syncthreads();

    if (threadIdx.x == 0) {
        float SE = 0.f, SG = 0.f;
        #pragma unroll
        for (int w = 0; w < TPB / 32; w++) { SE += re[w]; SG += rg[w]; }
        float mix = tanhf(SE + expert_b[(size_t)idx * H + row]);
        float z = SG + gate_b[row];
        float g = 1.f / (1.f + expf(-z));
        float xv = x[row];
        out[row] = g * mix + (1.f - g) * xv;
    }

    // ---- Self-cleaning reset: last block restores globals for next replay ----
    __syncthreads();
    if (threadIdx.x == 0) {
        int d = atomicAdd(&g_done, 1);
        if (d == GRID - 1) {
            g_done = 0;
            g_rcnt = 0;
            g_best = 0ULL;
            __threadfence();
        }
    }
}

extern "C" void kernel_launch(void* const* d_in, const int* in_sizes, int n_in,
                              void* d_out, int out_size) {
    const float* x        = (const float*)d_in[0];  // [1, H]
    const float* expert_w = (const float*)d_in[1];  // [E, H, H]
    const float* expert_b = (const float*)d_in[2];  // [E, H]
    const float* router_w = (const float*)d_in[3];  // [E, H]
    const float* router_b = (const float*)d_in[4];  // [E]
    const float* gate_w   = (const float*)d_in[5];  // [H, H]
    const float* gate_b   = (const float*)d_in[6];  // [H]
    float* out = (float*)d_out;                     // [1, H]

    fused_kernel<<<GRID, TPB>>>(x, expert_w, expert_b, router_w, router_b,
                                gate_w, gate_b, out);
}